// round 3
// baseline (speedup 1.0000x reference)
#include <cuda_runtime.h>
#include <math.h>

typedef unsigned long long ull;

#define EPSV 1e-4f
#define NB   16
#define HP   14
#define NP   196
#define TP   3136
#define PT   7            // patches per block (half feature row)
#define NBLK (TP/PT)      // 448
#define PROTO 60

// scratch (allocation-free: device globals)
__device__ float g_dist[NB*PROTO*NP];
__device__ float g_pact[NB*PROTO];

// transposed + k-pair-interleaved weights: g_Wt2[k2*O + o] = pack(W[o][2k2], W[o][2k2+1])
__device__ ull g_Wft2[384*512];
__device__ ull g_W1t2[256*256];
__device__ ull g_W2t2[128*256];
__device__ ull g_W3t2[128*128];
__device__ ull g_W4t2[ 64*128];

// ---------------------------------------------------------------------------
// f32x2 packed helpers
// ---------------------------------------------------------------------------
__device__ __forceinline__ ull pk(float lo, float hi) {
    ull r; asm("mov.b64 %0, {%1,%2};" : "=l"(r) : "f"(lo), "f"(hi)); return r;
}
__device__ __forceinline__ float2 upk(ull v) {
    float2 r; asm("mov.b64 {%0,%1}, %2;" : "=f"(r.x), "=f"(r.y) : "l"(v)); return r;
}
__device__ __forceinline__ void fma2(ull& d, ull a, ull b) {
    asm("fma.rn.f32x2 %0, %1, %2, %0;" : "+l"(d) : "l"(a), "l"(b));
}

// ---------------------------------------------------------------------------
// K0: tiled transpose of all weight matrices into paired [k2][o] layout.
// One block = one 32(o) x 32(k) tile. Both gmem sides coalesced.
// ---------------------------------------------------------------------------
__global__ __launch_bounds__(256) void k_tr(
    const float* __restrict__ Wf, const float* __restrict__ W1,
    const float* __restrict__ W2, const float* __restrict__ W3,
    const float* __restrict__ W4)
{
    __shared__ float tile[32][33];
    int bid = blockIdx.x;
    const float* src; ull* dst; int O, K, ot, kt;
    if (bid < 384)      { src=Wf; dst=g_Wft2; O=512; K=768; int r=bid;     ot=r/24; kt=r%24; }
    else if (bid < 512) { src=W1; dst=g_W1t2; O=256; K=512; int r=bid-384; ot=r/16; kt=r%16; }
    else if (bid < 576) { src=W2; dst=g_W2t2; O=256; K=256; int r=bid-512; ot=r/8;  kt=r%8;  }
    else if (bid < 608) { src=W3; dst=g_W3t2; O=128; K=256; int r=bid-576; ot=r/8;  kt=r%8;  }
    else                { src=W4; dst=g_W4t2; O=128; K=128; int r=bid-608; ot=r/4;  kt=r%4;  }
    int o0 = ot*32, k0 = kt*32;

    int tx = threadIdx.x & 31;   // k within tile
    int ty = threadIdx.x >> 5;   // o slice
    #pragma unroll
    for (int s = 0; s < 4; s++) {
        int oy = ty + s*8;
        tile[tx][oy] = src[(size_t)(o0+oy)*K + k0 + tx];
    }
    __syncthreads();

    int oL  = threadIdx.x & 31;
    int k2b = threadIdx.x >> 5;  // 0..7
    #pragma unroll
    for (int s = 0; s < 2; s++) {
        int k2L = k2b + s*8;     // 0..15
        float lo = tile[2*k2L][oL];
        float hi = tile[2*k2L+1][oL];
        dst[(size_t)(k0/2 + k2L)*O + o0 + oL] = pk(lo, hi);
    }
}

// ---------------------------------------------------------------------------
// K1: fused patch-conv + MLP + distances + act + 16x upsample stores.
// One block = 7 patches (half of one feature row): b, py, px0 in {0,7}.
// All FMA work done as packed fma.rn.f32x2 over k-pairs.
// ---------------------------------------------------------------------------
__global__ __launch_bounds__(256, 2) void k_mlp(
    const float* __restrict__ x,
    const float* __restrict__ bf, const float* __restrict__ b1,
    const float* __restrict__ b2, const float* __restrict__ b3,
    const float* __restrict__ b4, const float* __restrict__ prot,
    float* __restrict__ out_up)
{
    extern __shared__ float sm[];
    float* sA = sm;              // 7*768 floats (21KB); reused for h2 (7*256)
    float* sB = sm + PT*768;     // 7*512 (14KB);        reused h3 + sAct
    float* sC = sB + PT*512;     // 7*256 (7KB);         h1, then h4

    const int tid = threadIdx.x;
    const int hb  = blockIdx.x;
    const int b   = hb / 28;
    const int rem = hb - b*28;
    const int py  = rem >> 1;
    const int px0 = (rem & 1) * 7;

    // ---- load 7 patches (3x16x16) into sA
    for (int e = tid; e < PT*768; e += 256) {
        int pt = e / 768, k = e - pt*768;
        int c = k >> 8, r = (k >> 4) & 15, col = k & 15;
        sA[e] = x[((b*3 + c)*224 + py*16 + r)*224 + (px0 + pt)*16 + col];
    }
    __syncthreads();

    // ---- stage 0: 512 outputs, K=768 : sA -> sB (2 passes of 256 outputs)
    #pragma unroll 1
    for (int pass = 0; pass < 2; pass++) {
        const int o = tid + pass*256;
        ull acc[PT];
        #pragma unroll
        for (int pt = 0; pt < PT; pt++) acc[pt] = 0ull;
        #pragma unroll 2
        for (int k = 0; k < 768; k += 4) {
            ull w01 = g_Wft2[(k>>1)*512 + o];
            ull w23 = g_Wft2[((k>>1)+1)*512 + o];
            #pragma unroll
            for (int pt = 0; pt < PT; pt++) {
                float4 a = *(const float4*)&sA[pt*768 + k];
                fma2(acc[pt], pk(a.x, a.y), w01);
                fma2(acc[pt], pk(a.z, a.w), w23);
            }
        }
        float bb = bf[o];
        #pragma unroll
        for (int pt = 0; pt < PT; pt++) {
            float2 s = upk(acc[pt]);
            sB[pt*512 + o] = fmaxf(s.x + s.y + bb, 0.f);
        }
    }
    __syncthreads();

    // ---- stage 1: 256 outputs, K=512 : sB -> sC
    {
        ull acc[PT];
        #pragma unroll
        for (int pt = 0; pt < PT; pt++) acc[pt] = 0ull;
        #pragma unroll 2
        for (int k = 0; k < 512; k += 4) {
            ull w01 = g_W1t2[(k>>1)*256 + tid];
            ull w23 = g_W1t2[((k>>1)+1)*256 + tid];
            #pragma unroll
            for (int pt = 0; pt < PT; pt++) {
                float4 a = *(const float4*)&sB[pt*512 + k];
                fma2(acc[pt], pk(a.x, a.y), w01);
                fma2(acc[pt], pk(a.z, a.w), w23);
            }
        }
        float bb = b1[tid];
        #pragma unroll
        for (int pt = 0; pt < PT; pt++) {
            float2 s = upk(acc[pt]);
            sC[pt*256 + tid] = fmaxf(s.x + s.y + bb, 0.f);
        }
    }
    __syncthreads();

    // ---- stage 2: 256 outputs, K=256 : sC -> sA (reuse)
    {
        ull acc[PT];
        #pragma unroll
        for (int pt = 0; pt < PT; pt++) acc[pt] = 0ull;
        #pragma unroll 2
        for (int k = 0; k < 256; k += 4) {
            ull w01 = g_W2t2[(k>>1)*256 + tid];
            ull w23 = g_W2t2[((k>>1)+1)*256 + tid];
            #pragma unroll
            for (int pt = 0; pt < PT; pt++) {
                float4 a = *(const float4*)&sC[pt*256 + k];
                fma2(acc[pt], pk(a.x, a.y), w01);
                fma2(acc[pt], pk(a.z, a.w), w23);
            }
        }
        float bb = b2[tid];
        #pragma unroll
        for (int pt = 0; pt < PT; pt++) {
            float2 s = upk(acc[pt]);
            sA[pt*256 + tid] = fmaxf(s.x + s.y + bb, 0.f);
        }
    }
    __syncthreads();

    // ---- stage 3: 128 outputs, K=256 : sA -> sB (thread: 1 out x 3-4 patches)
    {
        const int o   = tid & 127;
        const int ph  = tid >> 7;
        const int pt0 = ph * 4;
        const int npt = ph ? 3 : 4;
        ull acc[4] = {0ull, 0ull, 0ull, 0ull};
        #pragma unroll 2
        for (int k = 0; k < 256; k += 4) {
            ull w01 = g_W3t2[(k>>1)*128 + o];
            ull w23 = g_W3t2[((k>>1)+1)*128 + o];
            #pragma unroll
            for (int j = 0; j < 4; j++) {   // j=3,ph=1 reads in-bounds garbage, never stored
                float4 a = *(const float4*)&sA[(pt0 + j)*256 + k];
                fma2(acc[j], pk(a.x, a.y), w01);
                fma2(acc[j], pk(a.z, a.w), w23);
            }
        }
        float bb = b3[o];
        #pragma unroll
        for (int j = 0; j < 4; j++) if (j < npt) {
            float2 s = upk(acc[j]);
            sB[(pt0 + j)*128 + o] = fmaxf(s.x + s.y + bb, 0.f);
        }
    }
    __syncthreads();

    // ---- stage 4: 128 outputs, K=128, sigmoid : sB -> sC
    {
        const int o   = tid & 127;
        const int ph  = tid >> 7;
        const int pt0 = ph * 4;
        const int npt = ph ? 3 : 4;
        ull acc[4] = {0ull, 0ull, 0ull, 0ull};
        #pragma unroll 2
        for (int k = 0; k < 128; k += 4) {
            ull w01 = g_W4t2[(k>>1)*128 + o];
            ull w23 = g_W4t2[((k>>1)+1)*128 + o];
            #pragma unroll
            for (int j = 0; j < 4; j++) {
                float4 a = *(const float4*)&sB[(pt0 + j)*128 + k];
                fma2(acc[j], pk(a.x, a.y), w01);
                fma2(acc[j], pk(a.z, a.w), w23);
            }
        }
        float bb = b4[o];
        #pragma unroll
        for (int j = 0; j < 4; j++) if (j < npt) {
            float2 s = upk(acc[j]);
            float z = s.x + s.y + bb;
            sC[(pt0 + j)*128 + o] = 1.0f / (1.0f + expf(-z));
        }
    }
    __syncthreads();

    // ---- distances + act (60 protos x 7 patches) : sC -> g_dist, sAct (in sB)
    float* sAct = sB;   // 420 floats, sB free now
    for (int q = tid; q < PROTO*PT; q += 256) {
        int p = q / PT, pt = q - p*PT;
        const float* pr = prot + p*128;
        const float* hh = sC + pt*128;
        float acc = 0.f;
        #pragma unroll 8
        for (int k = 0; k < 128; k += 4) {
            float4 h4 = *(const float4*)&hh[k];
            float4 p4 = *(const float4*)&pr[k];
            float d0 = h4.x - p4.x, d1 = h4.y - p4.y;
            float d2 = h4.z - p4.z, d3 = h4.w - p4.w;
            acc = fmaf(d0, d0, acc); acc = fmaf(d1, d1, acc);
            acc = fmaf(d2, d2, acc); acc = fmaf(d3, d3, acc);
        }
        float d = sqrtf(acc);
        g_dist[(b*PROTO + p)*NP + py*HP + px0 + pt] = d;
        sAct[q] = logf((d + 1.0f) / (d + EPSV));
    }
    __syncthreads();

    // ---- fused 16x upsample: 60 protos x 16 rows x 28 float4 = 26880 stores
    for (int t = tid; t < PROTO*16*28; t += 256) {
        int p    = t / 448;
        int rem2 = t - p*448;
        int r    = rem2 / 28;
        int c4   = rem2 - r*28;
        float v  = sAct[p*PT + (c4 >> 2)];
        size_t rowbase = ((size_t)(b*PROTO + p)*224 + py*16 + r)*224 + (size_t)px0*16;
        *(float4*)(out_up + rowbase + c4*4) = make_float4(v, v, v, v);
    }
}

// ---------------------------------------------------------------------------
// K2: per-(b,p) top-k smallest distances; act monotone-decreasing in d so the
// same indices serve both outputs. One warp per task.
// ---------------------------------------------------------------------------
__global__ void k_topk(const int* __restrict__ kptr, float* __restrict__ out_mind)
{
    const int k = *kptr;
    const int warp = (blockIdx.x * blockDim.x + threadIdx.x) >> 5;
    const int lane = threadIdx.x & 31;
    if (warp >= NB*PROTO) return;

    const float* dp = g_dist + warp*NP;
    float v[7];
    #pragma unroll
    for (int j = 0; j < 7; j++) {
        int i = lane + 32*j;
        v[j] = (i < NP) ? dp[i] : 1e30f;
    }

    float sd = 0.f, sa = 0.f;
    for (int it = 0; it < k; it++) {
        float m = v[0]; int mj = 0;
        #pragma unroll
        for (int j = 1; j < 7; j++) if (v[j] < m) { m = v[j]; mj = j; }
        float bm = m; int bidx = (mj << 5) | lane;
        #pragma unroll
        for (int off = 16; off; off >>= 1) {
            float om = __shfl_xor_sync(0xffffffffu, bm, off);
            int   oi = __shfl_xor_sync(0xffffffffu, bidx, off);
            if (om < bm || (om == bm && oi < bidx)) { bm = om; bidx = oi; }
        }
        sd += bm;
        sa += logf((bm + 1.0f) / (bm + EPSV));
        if (lane == (bidx & 31)) v[bidx >> 5] = 1e30f;
    }
    if (lane == 0) {
        out_mind[warp] = sd / (float)k;
        g_pact[warp]   = sa / (float)k;
    }
}

// ---------------------------------------------------------------------------
// K3: logits via smem-staged dot products (kills serial DRAM latency).
// ---------------------------------------------------------------------------
__global__ __launch_bounds__(256) void k_logits(const float* __restrict__ lastW,
                                                float* __restrict__ out)
{
    __shared__ float sp[NB*PROTO];
    __shared__ float sw[3*PROTO];
    for (int i = threadIdx.x; i < NB*PROTO; i += 256) sp[i] = g_pact[i];
    for (int i = threadIdx.x; i < 3*PROTO;  i += 256) sw[i] = lastW[i];
    __syncthreads();
    int t = threadIdx.x;
    if (t < NB*3) {
        int b = t / 3, c = t - b*3;
        float s = 0.f;
        #pragma unroll
        for (int p = 0; p < PROTO; p++)
            s += sp[b*PROTO + p] * sw[c*PROTO + p];
        out[t] = s;
    }
}

// ---------------------------------------------------------------------------
extern "C" void kernel_launch(void* const* d_in, const int* in_sizes, int n_in,
                              void* d_out, int out_size)
{
    const float* x    = (const float*)d_in[0];
    // d_in[1] = mascaras (unused by reference)
    const float* Wf   = (const float*)d_in[2];
    const float* bf   = (const float*)d_in[3];
    const float* W1   = (const float*)d_in[4];
    const float* b1   = (const float*)d_in[5];
    const float* W2   = (const float*)d_in[6];
    const float* b2   = (const float*)d_in[7];
    const float* W3   = (const float*)d_in[8];
    const float* b3   = (const float*)d_in[9];
    const float* W4   = (const float*)d_in[10];
    const float* b4   = (const float*)d_in[11];
    const float* prot = (const float*)d_in[12];
    const float* lastW= (const float*)d_in[13];
    const int*   kptr = (const int*)d_in[14];
    float* out = (float*)d_out;

    const int SMEM = (PT*768 + PT*512 + PT*256) * 4;   // 43008 bytes
    cudaFuncSetAttribute(k_mlp, cudaFuncAttributeMaxDynamicSharedMemorySize, SMEM);

    // output packing: logits[48] | min_distances[960] | upsampled[16*60*224*224]
    k_tr    <<<624, 256>>>(Wf, W1, W2, W3, W4);
    k_mlp   <<<NBLK, 256, SMEM>>>(x, bf, b1, b2, b3, b4, prot, out + 48 + NB*PROTO);
    k_topk  <<<(NB*PROTO*32 + 255)/256, 256>>>(kptr, out + 48);
    k_logits<<<1, 256>>>(lastW, out);
}

// round 4
// speedup vs baseline: 1.2013x; 1.2013x over previous
#include <cuda_runtime.h>
#include <math.h>

typedef unsigned long long ull;

#define EPSV 1e-4f
#define NB   16
#define HP   14
#define NP   196
#define TP   3136
#define PT   16           // patches per block
#define NBLK (TP/PT)      // 196
#define PROTO 60

// scratch (allocation-free: device globals)
__device__ float g_dist[NB*PROTO*NP];

// transposed + k-pair-interleaved weights: g_Wt2[k2*O + o] = pack(W[o][2k2], W[o][2k2+1])
__device__ ull g_Wft2[384*512];
__device__ ull g_W1t2[256*256];
__device__ ull g_W2t2[128*256];
__device__ ull g_W3t2[128*128];
__device__ ull g_W4t2[ 64*128];

// ---------------------------------------------------------------------------
__device__ __forceinline__ ull pk(float lo, float hi) {
    ull r; asm("mov.b64 %0, {%1,%2};" : "=l"(r) : "f"(lo), "f"(hi)); return r;
}
__device__ __forceinline__ float2 upk(ull v) {
    float2 r; asm("mov.b64 {%0,%1}, %2;" : "=f"(r.x), "=f"(r.y) : "l"(v)); return r;
}
__device__ __forceinline__ void fma2(ull& d, ull a, ull b) {
    asm("fma.rn.f32x2 %0, %1, %2, %0;" : "+l"(d) : "l"(a), "l"(b));
}

// ---------------------------------------------------------------------------
// K0: tiled transpose of weight matrices into paired [k2][o] layout.
// ---------------------------------------------------------------------------
__global__ __launch_bounds__(256) void k_tr(
    const float* __restrict__ Wf, const float* __restrict__ W1,
    const float* __restrict__ W2, const float* __restrict__ W3,
    const float* __restrict__ W4)
{
    __shared__ float tile[32][33];
    int bid = blockIdx.x;
    const float* src; ull* dst; int O, K, ot, kt;
    if (bid < 384)      { src=Wf; dst=g_Wft2; O=512; K=768; int r=bid;     ot=r/24; kt=r%24; }
    else if (bid < 512) { src=W1; dst=g_W1t2; O=256; K=512; int r=bid-384; ot=r/16; kt=r%16; }
    else if (bid < 576) { src=W2; dst=g_W2t2; O=256; K=256; int r=bid-512; ot=r/8;  kt=r%8;  }
    else if (bid < 608) { src=W3; dst=g_W3t2; O=128; K=256; int r=bid-576; ot=r/8;  kt=r%8;  }
    else                { src=W4; dst=g_W4t2; O=128; K=128; int r=bid-608; ot=r/4;  kt=r%4;  }
    int o0 = ot*32, k0 = kt*32;

    int tx = threadIdx.x & 31;
    int ty = threadIdx.x >> 5;
    #pragma unroll
    for (int s = 0; s < 4; s++) {
        int oy = ty + s*8;
        tile[tx][oy] = src[(size_t)(o0+oy)*K + k0 + tx];
    }
    __syncthreads();

    int oL  = threadIdx.x & 31;
    int k2b = threadIdx.x >> 5;
    #pragma unroll
    for (int s = 0; s < 2; s++) {
        int k2L = k2b + s*8;
        dst[(size_t)(k0/2 + k2L)*O + o0 + oL] = pk(tile[2*k2L][oL], tile[2*k2L+1][oL]);
    }
}

// ---------------------------------------------------------------------------
// K1: fused patch-conv + MLP + distances + act + 16x upsample.
// One block = 16 consecutive patches. All GEMM work as packed fma.rn.f32x2,
// activation pairs loaded directly as ulonglong2 (no pack instructions).
// ---------------------------------------------------------------------------
__global__ __launch_bounds__(256, 2) void k_mlp(
    const float* __restrict__ x,
    const float* __restrict__ bf, const float* __restrict__ b1,
    const float* __restrict__ b2, const float* __restrict__ b3,
    const float* __restrict__ b4, const float* __restrict__ prot,
    float* __restrict__ out_up)
{
    extern __shared__ float sm[];
    float* sA = sm;              // 16*768 (48KB); reused as h2 (16*256)
    float* sB = sm + PT*768;     // 16*512 (32KB); reused as h3, then sAct
    float* sC = sB + PT*512;     // 16*256 (16KB); h1, then h4

    const int tid = threadIdx.x;
    const int gp0 = blockIdx.x * PT;

    // ---- load 16 patches (3x16x16 each) into sA[pt][k]
    for (int e = tid; e < PT*768; e += 256) {
        int pt = e >> 9; pt = e / 768;           // (kept simple)
        int k = e - pt*768;
        int c = k >> 8, r = (k >> 4) & 15, col = k & 15;
        int gp = gp0 + pt;
        int b = gp / NP, hw = gp - b*NP;
        int py = hw / HP, px = hw - py*HP;
        sA[e] = x[((b*3 + c)*224 + py*16 + r)*224 + px*16 + col];
    }
    __syncthreads();

    // ---- stage 0: 512 outputs, K=768 : sA -> sB. Two passes of 256 outputs;
    //      each pass reads its own weight half exactly once (no re-read).
    #pragma unroll 1
    for (int pass = 0; pass < 2; pass++) {
        const int o = tid + pass*256;
        ull acc[PT];
        #pragma unroll
        for (int pt = 0; pt < PT; pt++) acc[pt] = 0ull;
        #pragma unroll 1
        for (int k = 0; k < 768; k += 4) {
            ull w01 = g_Wft2[(k>>1)*512 + o];
            ull w23 = g_Wft2[((k>>1)+1)*512 + o];
            #pragma unroll
            for (int pt = 0; pt < PT; pt++) {
                ulonglong2 a = *(const ulonglong2*)&sA[pt*768 + k];
                fma2(acc[pt], a.x, w01);
                fma2(acc[pt], a.y, w23);
            }
        }
        float bb = bf[o];
        #pragma unroll
        for (int pt = 0; pt < PT; pt++) {
            float2 s = upk(acc[pt]);
            sB[pt*512 + o] = fmaxf(s.x + s.y + bb, 0.f);
        }
    }
    __syncthreads();

    // ---- stage 1: 256 outputs, K=512 : sB -> sC.
    //      Thread (o = tid&127, ph = tid>>7) computes outs {o, o+128} over 8 pts.
    {
        const int o  = tid & 127;
        const int p0 = (tid >> 7) * 8;
        ull acc0[8], acc1[8];
        #pragma unroll
        for (int j = 0; j < 8; j++) { acc0[j] = 0ull; acc1[j] = 0ull; }
        #pragma unroll 1
        for (int k = 0; k < 512; k += 4) {
            ull wa01 = g_W1t2[(k>>1)*256 + o];
            ull wa23 = g_W1t2[((k>>1)+1)*256 + o];
            ull wb01 = g_W1t2[(k>>1)*256 + o + 128];
            ull wb23 = g_W1t2[((k>>1)+1)*256 + o + 128];
            #pragma unroll
            for (int j = 0; j < 8; j++) {
                ulonglong2 a = *(const ulonglong2*)&sB[(p0+j)*512 + k];
                fma2(acc0[j], a.x, wa01); fma2(acc0[j], a.y, wa23);
                fma2(acc1[j], a.x, wb01); fma2(acc1[j], a.y, wb23);
            }
        }
        float bb0 = b1[o], bb1 = b1[o + 128];
        #pragma unroll
        for (int j = 0; j < 8; j++) {
            float2 s0 = upk(acc0[j]), s1 = upk(acc1[j]);
            sC[(p0+j)*256 + o]       = fmaxf(s0.x + s0.y + bb0, 0.f);
            sC[(p0+j)*256 + o + 128] = fmaxf(s1.x + s1.y + bb1, 0.f);
        }
    }
    __syncthreads();

    // ---- stage 2: 256 outputs, K=256 : sC -> sA (reuse)
    {
        const int o  = tid & 127;
        const int p0 = (tid >> 7) * 8;
        ull acc0[8], acc1[8];
        #pragma unroll
        for (int j = 0; j < 8; j++) { acc0[j] = 0ull; acc1[j] = 0ull; }
        #pragma unroll 1
        for (int k = 0; k < 256; k += 4) {
            ull wa01 = g_W2t2[(k>>1)*256 + o];
            ull wa23 = g_W2t2[((k>>1)+1)*256 + o];
            ull wb01 = g_W2t2[(k>>1)*256 + o + 128];
            ull wb23 = g_W2t2[((k>>1)+1)*256 + o + 128];
            #pragma unroll
            for (int j = 0; j < 8; j++) {
                ulonglong2 a = *(const ulonglong2*)&sC[(p0+j)*256 + k];
                fma2(acc0[j], a.x, wa01); fma2(acc0[j], a.y, wa23);
                fma2(acc1[j], a.x, wb01); fma2(acc1[j], a.y, wb23);
            }
        }
        float bb0 = b2[o], bb1 = b2[o + 128];
        #pragma unroll
        for (int j = 0; j < 8; j++) {
            float2 s0 = upk(acc0[j]), s1 = upk(acc1[j]);
            sA[(p0+j)*256 + o]       = fmaxf(s0.x + s0.y + bb0, 0.f);
            sA[(p0+j)*256 + o + 128] = fmaxf(s1.x + s1.y + bb1, 0.f);
        }
    }
    __syncthreads();

    // ---- stage 3: 128 outputs, K=256 : sA -> sB. (o = tid&127, 8 pts each)
    {
        const int o  = tid & 127;
        const int p0 = (tid >> 7) * 8;
        ull acc[8];
        #pragma unroll
        for (int j = 0; j < 8; j++) acc[j] = 0ull;
        #pragma unroll 1
        for (int k = 0; k < 256; k += 4) {
            ull w01 = g_W3t2[(k>>1)*128 + o];
            ull w23 = g_W3t2[((k>>1)+1)*128 + o];
            #pragma unroll
            for (int j = 0; j < 8; j++) {
                ulonglong2 a = *(const ulonglong2*)&sA[(p0+j)*256 + k];
                fma2(acc[j], a.x, w01); fma2(acc[j], a.y, w23);
            }
        }
        float bb = b3[o];
        #pragma unroll
        for (int j = 0; j < 8; j++) {
            float2 s = upk(acc[j]);
            sB[(p0+j)*128 + o] = fmaxf(s.x + s.y + bb, 0.f);
        }
    }
    __syncthreads();

    // ---- stage 4: 128 outputs, K=128, sigmoid : sB -> sC
    {
        const int o  = tid & 127;
        const int p0 = (tid >> 7) * 8;
        ull acc[8];
        #pragma unroll
        for (int j = 0; j < 8; j++) acc[j] = 0ull;
        #pragma unroll 1
        for (int k = 0; k < 128; k += 4) {
            ull w01 = g_W4t2[(k>>1)*128 + o];
            ull w23 = g_W4t2[((k>>1)+1)*128 + o];
            #pragma unroll
            for (int j = 0; j < 8; j++) {
                ulonglong2 a = *(const ulonglong2*)&sB[(p0+j)*128 + k];
                fma2(acc[j], a.x, w01); fma2(acc[j], a.y, w23);
            }
        }
        float bb = b4[o];
        #pragma unroll
        for (int j = 0; j < 8; j++) {
            float2 s = upk(acc[j]);
            float z = s.x + s.y + bb;
            sC[(p0+j)*128 + o] = 1.0f / (1.0f + expf(-z));
        }
    }
    __syncthreads();

    // ---- distances + act (60 protos x 16 patches) : sC -> g_dist, sAct(=sB)
    float* sAct = sB;                 // PROTO*PT = 960 floats
    for (int q = tid; q < PROTO*PT; q += 256) {
        int p = q >> 4, pt = q & 15;
        const float* pr = prot + p*128;
        const float* hh = sC + pt*128;
        float acc = 0.f;
        #pragma unroll 8
        for (int k = 0; k < 128; k += 4) {
            float4 h4 = *(const float4*)&hh[k];
            float4 p4 = *(const float4*)&pr[k];
            float d0 = h4.x - p4.x, d1 = h4.y - p4.y;
            float d2 = h4.z - p4.z, d3 = h4.w - p4.w;
            acc = fmaf(d0, d0, acc); acc = fmaf(d1, d1, acc);
            acc = fmaf(d2, d2, acc); acc = fmaf(d3, d3, acc);
        }
        float d = sqrtf(acc);
        int gp = gp0 + pt;
        int b = gp / NP, hw = gp - b*NP;
        g_dist[(b*PROTO + p)*NP + hw] = d;
        sAct[p*PT + pt] = logf((d + 1.0f) / (d + EPSV));
    }

    // per-patch output base offsets (without proto/row terms)
    __shared__ int s_base[PT];
    if (tid < PT) {
        int gp = gp0 + tid;
        int b = gp / NP, hw = gp - b*NP;
        int py = hw / HP, px = hw - py*HP;
        s_base[tid] = b*PROTO*224*224 + (py*16)*224 + px*16;
    }
    __syncthreads();

    // ---- fused 16x upsample: 60 protos x 16 pts x 16 rows x 4 float4 stores
    for (int t = tid; t < PROTO*PT*16*4; t += 256) {
        int c4 = t & 3;
        int r  = (t >> 2) & 15;
        int pt = (t >> 6) & 15;
        int p  = t >> 10;
        float v = sAct[p*PT + pt];
        int addr = s_base[pt] + p*50176 + r*224 + c4*4;
        *(float4*)(out_up + addr) = make_float4(v, v, v, v);
    }
}

// ---------------------------------------------------------------------------
// K2: per-batch top-k + logits in one kernel. One block per batch image,
// 16 warps; warp w handles protos p = w, w+16, ... (iterative min-extract;
// act is monotone-decreasing in d so the same indices serve both outputs).
// ---------------------------------------------------------------------------
__global__ __launch_bounds__(512) void k_tkl(
    const int* __restrict__ kptr, const float* __restrict__ lastW,
    float* __restrict__ out_log, float* __restrict__ out_mind)
{
    __shared__ float sp[PROTO];
    const int b    = blockIdx.x;
    const int warp = threadIdx.x >> 5;
    const int lane = threadIdx.x & 31;
    const int k    = *kptr;

    for (int p = warp; p < PROTO; p += 16) {
        const float* dp = g_dist + (b*PROTO + p)*NP;
        float v[7];
        #pragma unroll
        for (int j = 0; j < 7; j++) {
            int i = lane + 32*j;
            v[j] = (i < NP) ? dp[i] : 1e30f;
        }
        float sd = 0.f, sa = 0.f;
        for (int it = 0; it < k; it++) {
            float m = v[0]; int mj = 0;
            #pragma unroll
            for (int j = 1; j < 7; j++) if (v[j] < m) { m = v[j]; mj = j; }
            float bm = m; int bidx = (mj << 5) | lane;
            #pragma unroll
            for (int off = 16; off; off >>= 1) {
                float om = __shfl_xor_sync(0xffffffffu, bm, off);
                int   oi = __shfl_xor_sync(0xffffffffu, bidx, off);
                if (om < bm || (om == bm && oi < bidx)) { bm = om; bidx = oi; }
            }
            sd += bm;
            sa += logf((bm + 1.0f) / (bm + EPSV));
            if (lane == (bidx & 31)) v[bidx >> 5] = 1e30f;
        }
        if (lane == 0) {
            out_mind[b*PROTO + p] = sd / (float)k;
            sp[p] = sa / (float)k;
        }
    }
    __syncthreads();
    int t = threadIdx.x;
    if (t < 3) {
        float s = 0.f;
        #pragma unroll
        for (int p = 0; p < PROTO; p++)
            s += sp[p] * lastW[t*PROTO + p];
        out_log[b*3 + t] = s;
    }
}

// ---------------------------------------------------------------------------
extern "C" void kernel_launch(void* const* d_in, const int* in_sizes, int n_in,
                              void* d_out, int out_size)
{
    const float* x    = (const float*)d_in[0];
    // d_in[1] = mascaras (unused by reference)
    const float* Wf   = (const float*)d_in[2];
    const float* bf   = (const float*)d_in[3];
    const float* W1   = (const float*)d_in[4];
    const float* b1   = (const float*)d_in[5];
    const float* W2   = (const float*)d_in[6];
    const float* b2   = (const float*)d_in[7];
    const float* W3   = (const float*)d_in[8];
    const float* b3   = (const float*)d_in[9];
    const float* W4   = (const float*)d_in[10];
    const float* b4   = (const float*)d_in[11];
    const float* prot = (const float*)d_in[12];
    const float* lastW= (const float*)d_in[13];
    const int*   kptr = (const int*)d_in[14];
    float* out = (float*)d_out;

    const int SMEM = (PT*768 + PT*512 + PT*256) * 4;   // 98304 bytes
    cudaFuncSetAttribute(k_mlp, cudaFuncAttributeMaxDynamicSharedMemorySize, SMEM);

    // output packing: logits[48] | min_distances[960] | upsampled[16*60*224*224]
    k_tr <<<624, 256>>>(Wf, W1, W2, W3, W4);
    k_mlp<<<NBLK, 256, SMEM>>>(x, bf, b1, b2, b3, b4, prot, out + 48 + NB*PROTO);
    k_tkl<<<NB, 512>>>(kptr, lastW, out, out + 48);
}

// round 5
// speedup vs baseline: 1.4822x; 1.2339x over previous
#include <cuda_runtime.h>
#include <math.h>

#define EPSV 1e-4f
#define NB   16
#define HP   14
#define NP   196
#define TP   3136
#define PT   8            // patches per block
#define NBLK (TP/PT)      // 392
#define PROTO 60

// scratch (allocation-free: device globals)
__device__ float g_dist[NB*PROTO*NP];

// transposed weights: Wt[k][o] so per-k loads are coalesced across threads
__device__ float g_Wft[768*512];
__device__ float g_W1t[512*256];
__device__ float g_W2t[256*256];
__device__ float g_W3t[256*128];
__device__ float g_W4t[128*128];

// ---------------------------------------------------------------------------
// K0: tiled transpose of all weight matrices (both gmem sides coalesced).
// One block = one 32(o) x 32(k) tile.
// ---------------------------------------------------------------------------
__global__ __launch_bounds__(256) void k_tr(
    const float* __restrict__ Wf, const float* __restrict__ W1,
    const float* __restrict__ W2, const float* __restrict__ W3,
    const float* __restrict__ W4)
{
    __shared__ float tile[32][33];
    int bid = blockIdx.x;
    const float* src; float* dst; int O, K, ot, kt;
    if (bid < 384)      { src=Wf; dst=g_Wft; O=512; K=768; int r=bid;     ot=r/24; kt=r%24; }
    else if (bid < 512) { src=W1; dst=g_W1t; O=256; K=512; int r=bid-384; ot=r/16; kt=r%16; }
    else if (bid < 576) { src=W2; dst=g_W2t; O=256; K=256; int r=bid-512; ot=r/8;  kt=r%8;  }
    else if (bid < 608) { src=W3; dst=g_W3t; O=128; K=256; int r=bid-576; ot=r/8;  kt=r%8;  }
    else                { src=W4; dst=g_W4t; O=128; K=128; int r=bid-608; ot=r/4;  kt=r%4;  }
    int o0 = ot*32, k0 = kt*32;

    int tx = threadIdx.x & 31;   // k within tile
    int ty = threadIdx.x >> 5;   // o slice
    #pragma unroll
    for (int s = 0; s < 4; s++) {
        int oy = ty + s*8;
        tile[tx][oy] = src[(size_t)(o0+oy)*K + k0 + tx];
    }
    __syncthreads();

    int oL = threadIdx.x & 31;
    int kb = threadIdx.x >> 5;
    #pragma unroll
    for (int s = 0; s < 4; s++) {
        int kL = kb + s*8;
        dst[(size_t)(k0+kL)*O + o0 + oL] = tile[kL][oL];
    }
}

// ---------------------------------------------------------------------------
// K1: fused patch-conv + MLP + prototype distances + act + 16x upsample.
// One block = PT=8 patches. GEMM structure identical to the proven R2 kernel.
// ---------------------------------------------------------------------------
__global__ __launch_bounds__(256) void k_mlp(
    const float* __restrict__ x,
    const float* __restrict__ bf, const float* __restrict__ b1,
    const float* __restrict__ b2, const float* __restrict__ b3,
    const float* __restrict__ b4, const float* __restrict__ prot,
    float* __restrict__ out_up)
{
    extern __shared__ float sm[];
    float* sA = sm;            // PT*768 (24KB); reused as h2 PT*256
    float* sB = sm + PT*768;   // PT*512 (16KB); reused as h3, then sAct
    float* sC = sB + PT*512;   // PT*256 (8KB);  h1, then h4

    const int tid = threadIdx.x;
    const int gp0 = blockIdx.x * PT;

    // ---- load PT patches of input (3x16x16 each) into sA
    for (int e = tid; e < PT*768; e += 256) {
        int pt = e / 768, k = e - pt*768;
        int c = k >> 8, r = (k >> 4) & 15, col = k & 15;
        int gp = gp0 + pt;
        int b = gp / NP, hw = gp - b*NP;
        int py = hw / HP, px = hw - py*HP;
        sA[e] = x[((b*3 + c)*224 + py*16 + r)*224 + px*16 + col];
    }
    __syncthreads();

    // ---- stage 0: 512 outputs (2/thread), K=768 : sA -> sB
    {
        float acc0[PT], acc1[PT];
        #pragma unroll
        for (int pt = 0; pt < PT; pt++) { acc0[pt] = 0.f; acc1[pt] = 0.f; }
        #pragma unroll 2
        for (int k = 0; k < 768; k += 4) {
            float w00 = g_Wft[(k+0)*512 + tid];
            float w01 = g_Wft[(k+1)*512 + tid];
            float w02 = g_Wft[(k+2)*512 + tid];
            float w03 = g_Wft[(k+3)*512 + tid];
            float w10 = g_Wft[(k+0)*512 + tid + 256];
            float w11 = g_Wft[(k+1)*512 + tid + 256];
            float w12 = g_Wft[(k+2)*512 + tid + 256];
            float w13 = g_Wft[(k+3)*512 + tid + 256];
            #pragma unroll
            for (int pt = 0; pt < PT; pt++) {
                float4 a = *(const float4*)&sA[pt*768 + k];
                acc0[pt] = fmaf(w00, a.x, acc0[pt]);
                acc0[pt] = fmaf(w01, a.y, acc0[pt]);
                acc0[pt] = fmaf(w02, a.z, acc0[pt]);
                acc0[pt] = fmaf(w03, a.w, acc0[pt]);
                acc1[pt] = fmaf(w10, a.x, acc1[pt]);
                acc1[pt] = fmaf(w11, a.y, acc1[pt]);
                acc1[pt] = fmaf(w12, a.z, acc1[pt]);
                acc1[pt] = fmaf(w13, a.w, acc1[pt]);
            }
        }
        float bb0 = bf[tid], bb1 = bf[tid + 256];
        #pragma unroll
        for (int pt = 0; pt < PT; pt++) {
            sB[pt*512 + tid]       = fmaxf(acc0[pt] + bb0, 0.f);
            sB[pt*512 + tid + 256] = fmaxf(acc1[pt] + bb1, 0.f);
        }
    }
    __syncthreads();

    // ---- stage 1: 256 outputs, K=512 : sB -> sC
    {
        float acc[PT];
        #pragma unroll
        for (int pt = 0; pt < PT; pt++) acc[pt] = 0.f;
        #pragma unroll 2
        for (int k = 0; k < 512; k += 4) {
            float w0 = g_W1t[(k+0)*256 + tid];
            float w1 = g_W1t[(k+1)*256 + tid];
            float w2 = g_W1t[(k+2)*256 + tid];
            float w3 = g_W1t[(k+3)*256 + tid];
            #pragma unroll
            for (int pt = 0; pt < PT; pt++) {
                float4 a = *(const float4*)&sB[pt*512 + k];
                acc[pt] = fmaf(w0, a.x, acc[pt]);
                acc[pt] = fmaf(w1, a.y, acc[pt]);
                acc[pt] = fmaf(w2, a.z, acc[pt]);
                acc[pt] = fmaf(w3, a.w, acc[pt]);
            }
        }
        float bb = b1[tid];
        #pragma unroll
        for (int pt = 0; pt < PT; pt++)
            sC[pt*256 + tid] = fmaxf(acc[pt] + bb, 0.f);
    }
    __syncthreads();

    // ---- stage 2: 256 outputs, K=256 : sC -> sA (reuse)
    {
        float acc[PT];
        #pragma unroll
        for (int pt = 0; pt < PT; pt++) acc[pt] = 0.f;
        #pragma unroll 2
        for (int k = 0; k < 256; k += 4) {
            float w0 = g_W2t[(k+0)*256 + tid];
            float w1 = g_W2t[(k+1)*256 + tid];
            float w2 = g_W2t[(k+2)*256 + tid];
            float w3 = g_W2t[(k+3)*256 + tid];
            #pragma unroll
            for (int pt = 0; pt < PT; pt++) {
                float4 a = *(const float4*)&sC[pt*256 + k];
                acc[pt] = fmaf(w0, a.x, acc[pt]);
                acc[pt] = fmaf(w1, a.y, acc[pt]);
                acc[pt] = fmaf(w2, a.z, acc[pt]);
                acc[pt] = fmaf(w3, a.w, acc[pt]);
            }
        }
        float bb = b2[tid];
        #pragma unroll
        for (int pt = 0; pt < PT; pt++)
            sA[pt*256 + tid] = fmaxf(acc[pt] + bb, 0.f);
    }
    __syncthreads();

    // ---- stage 3: 128 outputs, K=256 : sA -> sB (thread: 1 out x 4 patches)
    {
        const int o = tid & 127;
        const int half = tid >> 7;
        float acc[4] = {0.f, 0.f, 0.f, 0.f};
        #pragma unroll 2
        for (int k = 0; k < 256; k += 4) {
            float w0 = g_W3t[(k+0)*128 + o];
            float w1 = g_W3t[(k+1)*128 + o];
            float w2 = g_W3t[(k+2)*128 + o];
            float w3 = g_W3t[(k+3)*128 + o];
            #pragma unroll
            for (int j = 0; j < 4; j++) {
                float4 a = *(const float4*)&sA[(half*4 + j)*256 + k];
                acc[j] = fmaf(w0, a.x, acc[j]);
                acc[j] = fmaf(w1, a.y, acc[j]);
                acc[j] = fmaf(w2, a.z, acc[j]);
                acc[j] = fmaf(w3, a.w, acc[j]);
            }
        }
        float bb = b3[o];
        #pragma unroll
        for (int j = 0; j < 4; j++)
            sB[(half*4 + j)*128 + o] = fmaxf(acc[j] + bb, 0.f);
    }
    __syncthreads();

    // ---- stage 4: 128 outputs, K=128, sigmoid : sB -> sC
    {
        const int o = tid & 127;
        const int half = tid >> 7;
        float acc[4] = {0.f, 0.f, 0.f, 0.f};
        #pragma unroll 2
        for (int k = 0; k < 128; k += 4) {
            float w0 = g_W4t[(k+0)*128 + o];
            float w1 = g_W4t[(k+1)*128 + o];
            float w2 = g_W4t[(k+2)*128 + o];
            float w3 = g_W4t[(k+3)*128 + o];
            #pragma unroll
            for (int j = 0; j < 4; j++) {
                float4 a = *(const float4*)&sB[(half*4 + j)*128 + k];
                acc[j] = fmaf(w0, a.x, acc[j]);
                acc[j] = fmaf(w1, a.y, acc[j]);
                acc[j] = fmaf(w2, a.z, acc[j]);
                acc[j] = fmaf(w3, a.w, acc[j]);
            }
        }
        float bb = b4[o];
        #pragma unroll
        for (int j = 0; j < 4; j++) {
            float z = acc[j] + bb;
            sC[(half*4 + j)*128 + o] = 1.0f / (1.0f + expf(-z));
        }
    }
    __syncthreads();

    // ---- distances + act (60 protos x 8 patches) : sC -> g_dist, sAct(=sB)
    float* sAct = sB;   // PROTO*PT = 480 floats; sB free now
    for (int q = tid; q < PROTO*PT; q += 256) {
        int p = q >> 3, pt = q & 7;
        const float* pr = prot + p*128;
        const float* hh = sC + pt*128;
        float acc = 0.f;
        #pragma unroll 8
        for (int k = 0; k < 128; k += 4) {
            float4 h4 = *(const float4*)&hh[k];
            float4 p4 = *(const float4*)&pr[k];
            float d0 = h4.x - p4.x, d1 = h4.y - p4.y;
            float d2 = h4.z - p4.z, d3 = h4.w - p4.w;
            acc = fmaf(d0, d0, acc); acc = fmaf(d1, d1, acc);
            acc = fmaf(d2, d2, acc); acc = fmaf(d3, d3, acc);
        }
        float d = sqrtf(acc);
        int gp = gp0 + pt;
        int b = gp / NP, hw = gp - b*NP;
        g_dist[(b*PROTO + p)*NP + hw] = d;
        sAct[p*PT + pt] = logf((d + 1.0f) / (d + EPSV));
    }

    // per-patch output base offsets
    __shared__ int s_base[PT];
    if (tid < PT) {
        int gp = gp0 + tid;
        int b = gp / NP, hw = gp - b*NP;
        int py = hw / HP, px = hw - py*HP;
        s_base[tid] = b*PROTO*224*224 + (py*16)*224 + px*16;
    }
    __syncthreads();

    // ---- fused 16x upsample: 60 protos x 8 pts x 16 rows x 4 float4 stores.
    // Ordering (c4, pt) innermost so a warp writes 8 adjacent 64B segments of
    // (usually) one output row -> near-contiguous 512B bursts.
    for (int t = tid; t < PROTO*PT*16*4; t += 256) {
        int c4 = t & 3;
        int pt = (t >> 2) & 7;
        int r  = (t >> 5) & 15;
        int p  = t >> 9;
        float v = sAct[p*PT + pt];
        int addr = s_base[pt] + p*50176 + r*224 + c4*4;
        *(float4*)(out_up + addr) = make_float4(v, v, v, v);
    }
}

// ---------------------------------------------------------------------------
// K2: per-batch top-k + logits. One block per image, 16 warps; warp w handles
// protos p = w, w+16, ... (act monotone-decreasing in d -> same indices).
// ---------------------------------------------------------------------------
__global__ __launch_bounds__(512) void k_tkl(
    const int* __restrict__ kptr, const float* __restrict__ lastW,
    float* __restrict__ out_log, float* __restrict__ out_mind)
{
    __shared__ float sp[PROTO];
    const int b    = blockIdx.x;
    const int warp = threadIdx.x >> 5;
    const int lane = threadIdx.x & 31;
    const int k    = *kptr;

    for (int p = warp; p < PROTO; p += 16) {
        const float* dp = g_dist + (b*PROTO + p)*NP;
        float v[7];
        #pragma unroll
        for (int j = 0; j < 7; j++) {
            int i = lane + 32*j;
            v[j] = (i < NP) ? dp[i] : 1e30f;
        }
        float sd = 0.f, sa = 0.f;
        for (int it = 0; it < k; it++) {
            float m = v[0]; int mj = 0;
            #pragma unroll
            for (int j = 1; j < 7; j++) if (v[j] < m) { m = v[j]; mj = j; }
            float bm = m; int bidx = (mj << 5) | lane;
            #pragma unroll
            for (int off = 16; off; off >>= 1) {
                float om = __shfl_xor_sync(0xffffffffu, bm, off);
                int   oi = __shfl_xor_sync(0xffffffffu, bidx, off);
                if (om < bm || (om == bm && oi < bidx)) { bm = om; bidx = oi; }
            }
            sd += bm;
            sa += logf((bm + 1.0f) / (bm + EPSV));
            if (lane == (bidx & 31)) v[bidx >> 5] = 1e30f;
        }
        if (lane == 0) {
            out_mind[b*PROTO + p] = sd / (float)k;
            sp[p] = sa / (float)k;
        }
    }
    __syncthreads();
    int t = threadIdx.x;
    if (t < 3) {
        float s = 0.f;
        #pragma unroll
        for (int p = 0; p < PROTO; p++)
            s += sp[p] * lastW[t*PROTO + p];
        out_log[b*3 + t] = s;
    }
}

// ---------------------------------------------------------------------------
extern "C" void kernel_launch(void* const* d_in, const int* in_sizes, int n_in,
                              void* d_out, int out_size)
{
    const float* x    = (const float*)d_in[0];
    // d_in[1] = mascaras (unused by reference)
    const float* Wf   = (const float*)d_in[2];
    const float* bf   = (const float*)d_in[3];
    const float* W1   = (const float*)d_in[4];
    const float* b1   = (const float*)d_in[5];
    const float* W2   = (const float*)d_in[6];
    const float* b2   = (const float*)d_in[7];
    const float* W3   = (const float*)d_in[8];
    const float* b3   = (const float*)d_in[9];
    const float* W4   = (const float*)d_in[10];
    const float* b4   = (const float*)d_in[11];
    const float* prot = (const float*)d_in[12];
    const float* lastW= (const float*)d_in[13];
    const int*   kptr = (const int*)d_in[14];
    float* out = (float*)d_out;

    const int SMEM = (PT*768 + PT*512 + PT*256) * 4;   // 49152 bytes
    cudaFuncSetAttribute(k_mlp, cudaFuncAttributeMaxDynamicSharedMemorySize, 64*1024);

    // output packing: logits[48] | min_distances[960] | upsampled[16*60*224*224]
    k_tr <<<624, 256>>>(Wf, W1, W2, W3, W4);
    k_mlp<<<NBLK, 256, SMEM>>>(x, bf, b1, b2, b3, b4, prot, out + 48 + NB*PROTO);
    k_tkl<<<NB, 512>>>(kptr, lastW, out, out + 48);
}